// round 11
// baseline (speedup 1.0000x reference)
#include <cuda_runtime.h>
#include <cuda_bf16.h>
#include <math.h>

#define D 128
#define C 64
#define ROWS_PER_TILE 128
#define THREADS_MAIN 512   // 16 warps, each owns 4 classes
#define GRID_MAIN 296      // 2 blocks/SM: exactly one wave on 148 SMs
#define LAMBDA_PROTO 0.5f

// -------- device scratch (zero at module load; last block re-zeroes) --------
__device__ float g_sums[C * D];
__device__ float g_counts[C];
__device__ float g_z2[C];
__device__ float g_ce;
__device__ unsigned int g_done;

#define ACC_ROW(k, xv, inv, z2)                                            \
    do {                                                                   \
        if ((k) == 0) {                                                    \
            a0.x = fmaf((xv).x, (inv), a0.x); a0.y = fmaf((xv).y, (inv), a0.y); \
            a0.z = fmaf((xv).z, (inv), a0.z); a0.w = fmaf((xv).w, (inv), a0.w); \
            c0 += 1.0f; q0 += (z2);                                        \
        } else if ((k) == 1) {                                             \
            a1.x = fmaf((xv).x, (inv), a1.x); a1.y = fmaf((xv).y, (inv), a1.y); \
            a1.z = fmaf((xv).z, (inv), a1.z); a1.w = fmaf((xv).w, (inv), a1.w); \
            c1 += 1.0f; q1 += (z2);                                        \
        } else if ((k) == 2) {                                             \
            a2.x = fmaf((xv).x, (inv), a2.x); a2.y = fmaf((xv).y, (inv), a2.y); \
            a2.z = fmaf((xv).z, (inv), a2.z); a2.w = fmaf((xv).w, (inv), a2.w); \
            c2 += 1.0f; q2 += (z2);                                        \
        } else {                                                           \
            a3.x = fmaf((xv).x, (inv), a3.x); a3.y = fmaf((xv).y, (inv), a3.y); \
            a3.z = fmaf((xv).z, (inv), a3.z); a3.w = fmaf((xv).w, (inv), a3.w); \
            c3 += 1.0f; q3 += (z2);                                        \
        }                                                                  \
    } while (0)

// ---------------------------------------------------------
__global__ __launch_bounds__(THREADS_MAIN, 2)
void fused_kernel(const float* __restrict__ emb,
                  const float* __restrict__ logits,
                  const unsigned int* __restrict__ lab_w, int N,
                  float* __restrict__ out)
{
    __shared__ float s_red[16];
    __shared__ float s_pc[2 * C];
    __shared__ unsigned int s_rank;

    const int tid  = threadIdx.x;
    const int wid  = tid >> 5;
    const int lane = tid & 31;
    const int base = wid * 4;          // warp owns classes [base, base+4)
    const int half = lane >> 4;        // CE: half-warp id (0/1)
    const int hl   = lane & 15;        // CE: lane within half

    // --- per-warp label dtype detection ---
    unsigned probe = lab_w[2 * lane + 1];
    const int lsh = (__ballot_sync(0xffffffffu, probe != 0u) == 0u) ? 1 : 0;

    float4 a0 = {0,0,0,0}, a1 = a0, a2 = a0, a3 = a0;
    float  c0 = 0, c1 = 0, c2 = 0, c3 = 0;
    float  q0 = 0, q1 = 0, q2 = 0, q3 = 0;
    float  ce_acc = 0.0f;

    const float4* emb4 = (const float4*)emb;
    const float4* lg4  = (const float4*)logits;   // 16 float4 per row (C=64)
    const int ntiles = (N + ROWS_PER_TILE - 1) / ROWS_PER_TILE;

    // =========== single pass: CE loads -> routing -> CE compute ===========
    for (int tile = blockIdx.x; tile < ntiles; tile += GRID_MAIN) {
        const int row0 = tile * ROWS_PER_TILE;

        // ---- CE loads hoisted: in flight during the routing section ----
        float4 v[4]; float gt[4]; bool has[4];
        #pragma unroll
        for (int u = 0; u < 4; ++u) {
            int r = row0 + wid * 8 + u * 2 + half;
            has[u] = r < N;
            if (has[u]) {
                v[u] = lg4[(size_t)r * (C / 4) + hl];
                int l = (int)lab_w[(size_t)r << lsh];
                gt[u] = logits[(size_t)r * C + l];   // broadcast, L1-hit
            } else {
                v[u] = make_float4(0.f, 0.f, 0.f, 0.f);
                gt[u] = 0.0f;
            }
        }

        // ---- proto: ballot ownership over the tile's 128 rows ----
        unsigned long long m128[2];
        {
            unsigned b[4];
            #pragma unroll
            for (int h = 0; h < 4; ++h) {
                int r = row0 + lane + 32 * h;
                int lv = (r < N) ? (int)lab_w[(size_t)r << lsh] : -1;
                b[h] = __ballot_sync(0xffffffffu, (unsigned)(lv - base) < 4u);
            }
            m128[0] = (unsigned long long)b[0] | ((unsigned long long)b[1] << 32);
            m128[1] = (unsigned long long)b[2] | ((unsigned long long)b[3] << 32);
        }

        // ---- matched rows, four-at-a-time (4 independent chains) ----
        #pragma unroll
        for (int part = 0; part < 2; ++part) {
            unsigned long long m = m128[part];
            const int pbase = row0 + part * 64;
            while (m) {
                int nb = 0;
                int r[4];
                #pragma unroll
                for (int j = 0; j < 4; ++j) {
                    if (m) {
                        r[j] = pbase + (int)(__ffsll((long long)m) - 1);
                        m &= m - 1;
                        nb = j + 1;
                    } else {
                        r[j] = r[0];
                    }
                }
                int kk[4];
                float4 x[4];
                #pragma unroll
                for (int j = 0; j < 4; ++j) {
                    kk[j] = (int)lab_w[(size_t)r[j] << lsh] - base;  // bcast
                    x[j]  = emb4[(size_t)r[j] * (D / 4) + lane];
                }
                float s[4];
                #pragma unroll
                for (int j = 0; j < 4; ++j)
                    s[j] = x[j].x*x[j].x + x[j].y*x[j].y + x[j].z*x[j].z + x[j].w*x[j].w;
                #pragma unroll
                for (int o = 16; o; o >>= 1) {
                    #pragma unroll
                    for (int j = 0; j < 4; ++j)
                        s[j] += __shfl_xor_sync(0xffffffffu, s[j], o);
                }
                #pragma unroll
                for (int j = 0; j < 4; ++j) {
                    if (j < nb) {
                        float inv = rsqrtf(fmaxf(s[j], 1e-24f)); // ==1/max(||x||,1e-12)
                        float z2  = s[j] * inv * inv;
                        ACC_ROW(kk[j], x[j], inv, z2);
                    }
                }
            }
        }

        // ---- CE compute (loads landed long ago) ----
        {
            float e[4];
            #pragma unroll
            for (int u = 0; u < 4; ++u)
                e[u] = __expf(v[u].x) + __expf(v[u].y)
                     + __expf(v[u].z) + __expf(v[u].w);
            #pragma unroll
            for (int o = 8; o; o >>= 1) {
                #pragma unroll
                for (int u = 0; u < 4; ++u)
                    e[u] += __shfl_xor_sync(0xffffffffu, e[u], o);
            }
            if (hl == 0) {
                #pragma unroll
                for (int u = 0; u < 4; ++u)
                    if (has[u]) ce_acc += __logf(e[u]) - gt[u];
            }
        }
    }

    // ---- flush per-class accumulators (one-shot) ----
    const int dbase = lane * 4;
    atomicAdd(&g_sums[(base + 0) * D + dbase + 0], a0.x);
    atomicAdd(&g_sums[(base + 0) * D + dbase + 1], a0.y);
    atomicAdd(&g_sums[(base + 0) * D + dbase + 2], a0.z);
    atomicAdd(&g_sums[(base + 0) * D + dbase + 3], a0.w);
    atomicAdd(&g_sums[(base + 1) * D + dbase + 0], a1.x);
    atomicAdd(&g_sums[(base + 1) * D + dbase + 1], a1.y);
    atomicAdd(&g_sums[(base + 1) * D + dbase + 2], a1.z);
    atomicAdd(&g_sums[(base + 1) * D + dbase + 3], a1.w);
    atomicAdd(&g_sums[(base + 2) * D + dbase + 0], a2.x);
    atomicAdd(&g_sums[(base + 2) * D + dbase + 1], a2.y);
    atomicAdd(&g_sums[(base + 2) * D + dbase + 2], a2.z);
    atomicAdd(&g_sums[(base + 2) * D + dbase + 3], a2.w);
    atomicAdd(&g_sums[(base + 3) * D + dbase + 0], a3.x);
    atomicAdd(&g_sums[(base + 3) * D + dbase + 1], a3.y);
    atomicAdd(&g_sums[(base + 3) * D + dbase + 2], a3.z);
    atomicAdd(&g_sums[(base + 3) * D + dbase + 3], a3.w);
    if (lane == 0) {
        atomicAdd(&g_counts[base + 0], c0); atomicAdd(&g_z2[base + 0], q0);
        atomicAdd(&g_counts[base + 1], c1); atomicAdd(&g_z2[base + 1], q1);
        atomicAdd(&g_counts[base + 2], c2); atomicAdd(&g_z2[base + 2], q2);
        atomicAdd(&g_counts[base + 3], c3); atomicAdd(&g_z2[base + 3], q3);
    }

    // ---- block CE reduce (lanes 0 and 16 hold partials) ----
    ce_acc += __shfl_xor_sync(0xffffffffu, ce_acc, 16);
    if (lane == 0) s_red[wid] = ce_acc;
    __syncthreads();
    if (tid == 0) {
        float s = 0.0f;
        #pragma unroll
        for (int i = 0; i < THREADS_MAIN / 32; ++i) s += s_red[i];
        atomicAdd(&g_ce, s);
        __threadfence();
        s_rank = atomicAdd(&g_done, 1u);
    }
    __syncthreads();

    // =========== last block: finalize + re-zero scratch ===========
    if (s_rank == GRID_MAIN - 1) {
        __threadfence();  // see all blocks' atomics

        #pragma unroll
        for (int cc = 0; cc < 4; ++cc) {
            int c = base + cc;
            float4 vv = ((const float4*)(g_sums + c * D))[lane];
            float dot = vv.x*vv.x + vv.y*vv.y + vv.z*vv.z + vv.w*vv.w;
            #pragma unroll
            for (int o = 16; o; o >>= 1)
                dot += __shfl_xor_sync(0xffffffffu, dot, o);
            if (lane == 0) {
                float cnt  = g_counts[c];
                float safe = fmaxf(cnt, 1.0f);
                float ssd  = g_z2[c] - dot / safe;
                bool valid = (cnt > 1.0f);
                s_pc[c]     = valid ? (ssd / safe) : 0.0f;
                s_pc[C + c] = valid ? 1.0f : 0.0f;
            }
        }
        __syncthreads();
        if (tid == 0) {
            float sp = 0.0f, nv = 0.0f;
            #pragma unroll
            for (int c = 0; c < C; ++c) { sp += s_pc[c]; nv += s_pc[C + c]; }
            float proto = sp / fmaxf(nv, 1.0f);
            float ce    = g_ce / (float)N;
            out[0] = (1.0f - LAMBDA_PROTO) * ce + LAMBDA_PROTO * proto;
        }

        // re-zero scratch for next graph replay
        for (int i = tid; i < C * D; i += THREADS_MAIN) g_sums[i] = 0.0f;
        if (tid < C) { g_counts[tid] = 0.0f; g_z2[tid] = 0.0f; }
        if (tid == 0) { g_ce = 0.0f; __threadfence(); g_done = 0u; }
    }
}

// ---------------------------------------------------------
extern "C" void kernel_launch(void* const* d_in, const int* in_sizes, int n_in,
                              void* d_out, int out_size) {
    const float* emb          = (const float*)d_in[0];
    const float* logits       = (const float*)d_in[1];
    const unsigned int* lab_w = (const unsigned int*)d_in[2];
    int N = in_sizes[2];

    fused_kernel<<<GRID_MAIN, THREADS_MAIN>>>(emb, logits, lab_w, N, (float*)d_out);
}

// round 13
// speedup vs baseline: 1.1521x; 1.1521x over previous
#include <cuda_runtime.h>
#include <cuda_bf16.h>
#include <math.h>

#define D 128
#define C 64
#define ROWS_PER_TILE 128
#define THREADS_MAIN 512   // 16 warps, each owns 4 classes
#define GRID_MAIN 296      // 2 blocks/SM: exactly one wave on 148 SMs
#define LAMBDA_PROTO 0.5f

// -------- device scratch (zero at module load; last block re-zeroes) --------
__device__ float g_sums[C * D];
__device__ float g_counts[C];
__device__ float g_z2[C];
__device__ float g_ce;
__device__ unsigned int g_done;

#define ACC_ROW(k, xv, inv, z2)                                            \
    do {                                                                   \
        if ((k) == 0) {                                                    \
            a0.x = fmaf((xv).x, (inv), a0.x); a0.y = fmaf((xv).y, (inv), a0.y); \
            a0.z = fmaf((xv).z, (inv), a0.z); a0.w = fmaf((xv).w, (inv), a0.w); \
            c0 += 1.0f; q0 += (z2);                                        \
        } else if ((k) == 1) {                                             \
            a1.x = fmaf((xv).x, (inv), a1.x); a1.y = fmaf((xv).y, (inv), a1.y); \
            a1.z = fmaf((xv).z, (inv), a1.z); a1.w = fmaf((xv).w, (inv), a1.w); \
            c1 += 1.0f; q1 += (z2);                                        \
        } else if ((k) == 2) {                                             \
            a2.x = fmaf((xv).x, (inv), a2.x); a2.y = fmaf((xv).y, (inv), a2.y); \
            a2.z = fmaf((xv).z, (inv), a2.z); a2.w = fmaf((xv).w, (inv), a2.w); \
            c2 += 1.0f; q2 += (z2);                                        \
        } else {                                                           \
            a3.x = fmaf((xv).x, (inv), a3.x); a3.y = fmaf((xv).y, (inv), a3.y); \
            a3.z = fmaf((xv).z, (inv), a3.z); a3.w = fmaf((xv).w, (inv), a3.w); \
            c3 += 1.0f; q3 += (z2);                                        \
        }                                                                  \
    } while (0)

// ---------------------------------------------------------
__global__ __launch_bounds__(THREADS_MAIN, 2)
void fused_kernel(const float* __restrict__ emb,
                  const float* __restrict__ logits,
                  const unsigned int* __restrict__ lab_w, int N,
                  float* __restrict__ out)
{
    __shared__ float s_red[16];
    __shared__ float s_pc[2 * C];
    __shared__ unsigned int s_rank;

    const int tid  = threadIdx.x;
    const int wid  = tid >> 5;
    const int lane = tid & 31;
    const int base = wid * 4;          // warp owns classes [base, base+4)
    const int half = lane >> 4;        // CE: half-warp id (0/1)
    const int hl   = lane & 15;        // CE: lane within half

    // --- per-warp label dtype detection ---
    unsigned probe = lab_w[2 * lane + 1];
    const int lsh = (__ballot_sync(0xffffffffu, probe != 0u) == 0u) ? 1 : 0;

    float4 a0 = {0,0,0,0}, a1 = a0, a2 = a0, a3 = a0;
    float  c0 = 0, c1 = 0, c2 = 0, c3 = 0;
    float  q0 = 0, q1 = 0, q2 = 0, q3 = 0;
    float  ce_acc = 0.0f;

    const float4* emb4 = (const float4*)emb;
    const float4* lg4  = (const float4*)logits;   // 16 float4 per row (C=64)
    const int ntiles = (N + ROWS_PER_TILE - 1) / ROWS_PER_TILE;

    // =========== single pass: proto routing + CE per tile ===========
    for (int tile = blockIdx.x; tile < ntiles; tile += GRID_MAIN) {
        const int row0 = tile * ROWS_PER_TILE;

        // ---- proto: ballot ownership over the tile's 128 rows ----
        unsigned long long m128[2];
        {
            unsigned b[4];
            #pragma unroll
            for (int h = 0; h < 4; ++h) {
                int r = row0 + lane + 32 * h;
                int lv = (r < N) ? (int)lab_w[(unsigned)(r << lsh)] : -1;
                b[h] = __ballot_sync(0xffffffffu, (unsigned)(lv - base) < 4u);
            }
            m128[0] = (unsigned long long)b[0] | ((unsigned long long)b[1] << 32);
            m128[1] = (unsigned long long)b[2] | ((unsigned long long)b[3] << 32);
        }

        // ---- matched rows, four-at-a-time; joint 4-row reduction ----
        #pragma unroll
        for (int part = 0; part < 2; ++part) {
            unsigned long long m = m128[part];
            const int pbase = row0 + part * 64;
            while (m) {
                int nb = 0;
                int r[4];
                #pragma unroll
                for (int j = 0; j < 4; ++j) {
                    if (m) {
                        r[j] = pbase + (int)(__ffsll((long long)m) - 1);
                        m &= m - 1;
                        nb = j + 1;
                    } else {
                        r[j] = r[0];
                    }
                }
                int kk[4];
                float4 x[4];
                #pragma unroll
                for (int j = 0; j < 4; ++j) {
                    kk[j] = (int)lab_w[(unsigned)(r[j] << lsh)] - base;  // bcast
                    x[j]  = emb4[(unsigned)(r[j] * (D / 4) + lane)];
                }
                float s[4];
                #pragma unroll
                for (int j = 0; j < 4; ++j)
                    s[j] = x[j].x*x[j].x + x[j].y*x[j].y + x[j].z*x[j].z + x[j].w*x[j].w;

                // joint reduction: 2 wide steps, then 8-lane groups finish one row each
                #pragma unroll
                for (int j = 0; j < 4; ++j) s[j] += __shfl_xor_sync(0xffffffffu, s[j], 16);
                #pragma unroll
                for (int j = 0; j < 4; ++j) s[j] += __shfl_xor_sync(0xffffffffu, s[j], 8);
                int g = lane >> 3;
                float t = (g & 2) ? ((g & 1) ? s[3] : s[2])
                                  : ((g & 1) ? s[1] : s[0]);
                t += __shfl_xor_sync(0xffffffffu, t, 4);
                t += __shfl_xor_sync(0xffffffffu, t, 2);
                t += __shfl_xor_sync(0xffffffffu, t, 1);
                s[0] = __shfl_sync(0xffffffffu, t, 0);
                s[1] = __shfl_sync(0xffffffffu, t, 8);
                s[2] = __shfl_sync(0xffffffffu, t, 16);
                s[3] = __shfl_sync(0xffffffffu, t, 24);

                #pragma unroll
                for (int j = 0; j < 4; ++j) {
                    if (j < nb) {
                        float inv = rsqrtf(fmaxf(s[j], 1e-24f)); // ==1/max(||x||,1e-12)
                        float z2  = s[j] * inv * inv;
                        ACC_ROW(kk[j], x[j], inv, z2);
                    }
                }
            }
        }

        // ---- CE: half-warp per row, 8 rows/warp/tile, gt direct load ----
        {
            float4 v[4]; float gt[4]; bool has[4];
            #pragma unroll
            for (int u = 0; u < 4; ++u) {
                int r = row0 + wid * 8 + u * 2 + half;
                has[u] = r < N;
                if (has[u]) {
                    v[u] = lg4[(unsigned)(r * (C / 4) + hl)];
                    int l = (int)lab_w[(unsigned)(r << lsh)];
                    gt[u] = logits[(unsigned)(r * C + l)];   // bcast, L1-hit
                } else {
                    v[u] = make_float4(0.f, 0.f, 0.f, 0.f);
                    gt[u] = 0.0f;
                }
            }
            float e[4];
            #pragma unroll
            for (int u = 0; u < 4; ++u)
                e[u] = __expf(v[u].x) + __expf(v[u].y)
                     + __expf(v[u].z) + __expf(v[u].w);
            #pragma unroll
            for (int o = 8; o; o >>= 1) {
                #pragma unroll
                for (int u = 0; u < 4; ++u)
                    e[u] += __shfl_xor_sync(0xffffffffu, e[u], o);
            }
            if (hl == 0) {
                #pragma unroll
                for (int u = 0; u < 4; ++u)
                    if (has[u]) ce_acc += __logf(e[u]) - gt[u];
            }
        }
    }

    // ---- flush per-class accumulators (one-shot) ----
    const int dbase = lane * 4;
    atomicAdd(&g_sums[(base + 0) * D + dbase + 0], a0.x);
    atomicAdd(&g_sums[(base + 0) * D + dbase + 1], a0.y);
    atomicAdd(&g_sums[(base + 0) * D + dbase + 2], a0.z);
    atomicAdd(&g_sums[(base + 0) * D + dbase + 3], a0.w);
    atomicAdd(&g_sums[(base + 1) * D + dbase + 0], a1.x);
    atomicAdd(&g_sums[(base + 1) * D + dbase + 1], a1.y);
    atomicAdd(&g_sums[(base + 1) * D + dbase + 2], a1.z);
    atomicAdd(&g_sums[(base + 1) * D + dbase + 3], a1.w);
    atomicAdd(&g_sums[(base + 2) * D + dbase + 0], a2.x);
    atomicAdd(&g_sums[(base + 2) * D + dbase + 1], a2.y);
    atomicAdd(&g_sums[(base + 2) * D + dbase + 2], a2.z);
    atomicAdd(&g_sums[(base + 2) * D + dbase + 3], a2.w);
    atomicAdd(&g_sums[(base + 3) * D + dbase + 0], a3.x);
    atomicAdd(&g_sums[(base + 3) * D + dbase + 1], a3.y);
    atomicAdd(&g_sums[(base + 3) * D + dbase + 2], a3.z);
    atomicAdd(&g_sums[(base + 3) * D + dbase + 3], a3.w);
    if (lane == 0) {
        atomicAdd(&g_counts[base + 0], c0); atomicAdd(&g_z2[base + 0], q0);
        atomicAdd(&g_counts[base + 1], c1); atomicAdd(&g_z2[base + 1], q1);
        atomicAdd(&g_counts[base + 2], c2); atomicAdd(&g_z2[base + 2], q2);
        atomicAdd(&g_counts[base + 3], c3); atomicAdd(&g_z2[base + 3], q3);
    }

    // ---- block CE reduce (lanes 0 and 16 hold partials) ----
    ce_acc += __shfl_xor_sync(0xffffffffu, ce_acc, 16);
    if (lane == 0) s_red[wid] = ce_acc;
    __syncthreads();
    if (tid == 0) {
        float s = 0.0f;
        #pragma unroll
        for (int i = 0; i < THREADS_MAIN / 32; ++i) s += s_red[i];
        atomicAdd(&g_ce, s);
        __threadfence();
        s_rank = atomicAdd(&g_done, 1u);
    }
    __syncthreads();

    // =========== last block: finalize + re-zero scratch ===========
    if (s_rank == GRID_MAIN - 1) {
        __threadfence();  // see all blocks' atomics

        #pragma unroll
        for (int cc = 0; cc < 4; ++cc) {
            int c = base + cc;
            float4 vv = ((const float4*)(g_sums + c * D))[lane];
            float dot = vv.x*vv.x + vv.y*vv.y + vv.z*vv.z + vv.w*vv.w;
            #pragma unroll
            for (int o = 16; o; o >>= 1)
                dot += __shfl_xor_sync(0xffffffffu, dot, o);
            if (lane == 0) {
                float cnt  = g_counts[c];
                float safe = fmaxf(cnt, 1.0f);
                float ssd  = g_z2[c] - dot / safe;
                bool valid = (cnt > 1.0f);
                s_pc[c]     = valid ? (ssd / safe) : 0.0f;
                s_pc[C + c] = valid ? 1.0f : 0.0f;
            }
        }
        __syncthreads();
        if (tid == 0) {
            float sp = 0.0f, nv = 0.0f;
            #pragma unroll
            for (int c = 0; c < C; ++c) { sp += s_pc[c]; nv += s_pc[C + c]; }
            float proto = sp / fmaxf(nv, 1.0f);
            float ce    = g_ce / (float)N;
            out[0] = (1.0f - LAMBDA_PROTO) * ce + LAMBDA_PROTO * proto;
        }

        // re-zero scratch for next graph replay
        for (int i = tid; i < C * D; i += THREADS_MAIN) g_sums[i] = 0.0f;
        if (tid < C) { g_counts[tid] = 0.0f; g_z2[tid] = 0.0f; }
        if (tid == 0) { g_ce = 0.0f; __threadfence(); g_done = 0u; }
    }
}

// ---------------------------------------------------------
extern "C" void kernel_launch(void* const* d_in, const int* in_sizes, int n_in,
                              void* d_out, int out_size) {
    const float* emb          = (const float*)d_in[0];
    const float* logits       = (const float*)d_in[1];
    const unsigned int* lab_w = (const unsigned int*)d_in[2];
    int N = in_sizes[2];

    fused_kernel<<<GRID_MAIN, THREADS_MAIN>>>(emb, logits, lab_w, N, (float*)d_out);
}